// round 10
// baseline (speedup 1.0000x reference)
#include <cuda_runtime.h>
#include <math_constants.h>

// Scratch (no device allocs allowed)
__device__ float g_map[32 * 2 * 64 * 64];   // [b][2][4096]
__device__ float g_scale[32 * 64 * 64];     // [b][4096]

#define NB 32
#define NC 256
#define HW 4096          // 64*64
#define HW4 1024         // HW / 4

#define NBG 4            // images per pipeline group
#define NGROUPS 8        // 32 / 4
#define N1 128           // K1 blocks per group (32 per image * 4)
#define N2 64            // K2 blocks per group (16 per image * 4)
#define N3 1024          // K3 blocks per group (256 planes per image * 4)
// one fat launch = [K1 group g | K2 group g-1 | K3 group g-2], 1216 blocks

// ---------------- stage bodies ----------------

__device__ __forceinline__ void k1_body(const float* __restrict__ x, int local, int g,
                                        float4 (*smax)[32], float4 (*ssum)[32]) {
    int lane = threadIdx.x & 31;
    int wrp  = threadIdx.x >> 5;
    int b    = g * NBG + (local >> 5);
    int p4   = ((local & 31) << 5) + lane;   // 0..1023

    const float4* __restrict__ xv = reinterpret_cast<const float4*>(x);
    size_t base = (size_t)b * (NC * HW4) + (size_t)(wrp << 5) * HW4 + p4;

    float4 mx = make_float4(-CUDART_INF_F, -CUDART_INF_F, -CUDART_INF_F, -CUDART_INF_F);
    float4 sm = make_float4(0.f, 0.f, 0.f, 0.f);

    #pragma unroll
    for (int c = 0; c < 32; c++) {
        float4 v = __ldcs(&xv[base + (size_t)c * HW4]);
        mx.x = fmaxf(mx.x, v.x); mx.y = fmaxf(mx.y, v.y);
        mx.z = fmaxf(mx.z, v.z); mx.w = fmaxf(mx.w, v.w);
        sm.x += v.x; sm.y += v.y; sm.z += v.z; sm.w += v.w;
    }

    smax[wrp][lane] = mx;
    ssum[wrp][lane] = sm;
    __syncthreads();

    if (wrp == 0) {
        float4 m = smax[0][lane];
        float4 s = ssum[0][lane];
        #pragma unroll
        for (int w = 1; w < 8; w++) {
            float4 m2 = smax[w][lane];
            float4 s2 = ssum[w][lane];
            m.x = fmaxf(m.x, m2.x); m.y = fmaxf(m.y, m2.y);
            m.z = fmaxf(m.z, m2.z); m.w = fmaxf(m.w, m2.w);
            s.x += s2.x; s.y += s2.y; s.z += s2.z; s.w += s2.w;
        }
        const float inv = 1.0f / (float)NC;
        s.x *= inv; s.y *= inv; s.z *= inv; s.w *= inv;

        float4* mv = reinterpret_cast<float4*>(g_map);
        mv[(size_t)b * 2048 + p4]        = m;
        mv[(size_t)b * 2048 + 1024 + p4] = s;
    }
}

__device__ __forceinline__ void k2_body(const float* __restrict__ w, int local, int g,
                                        float* sw) {
    if (threadIdx.x < 98) sw[threadIdx.x] = w[threadIdx.x];
    __syncthreads();

    int b  = g * NBG + (local >> 4);
    int hw = ((local & 15) << 8) + threadIdx.x;   // 0..4095
    int h  = hw >> 6;
    int wc = hw & 63;

    const float* __restrict__ mp = g_map + (size_t)b * 2 * HW;

    float acc = 0.f;
    #pragma unroll
    for (int ky = 0; ky < 7; ky++) {
        int hy = h + ky - 3;
        if (hy < 0 || hy >= 64) continue;
        #pragma unroll
        for (int kx = 0; kx < 7; kx++) {
            int wx = wc + kx - 3;
            if (wx < 0 || wx >= 64) continue;
            int q = hy * 64 + wx;
            acc = fmaf(sw[ky * 7 + kx],      __ldg(&mp[q]),      acc);
            acc = fmaf(sw[49 + ky * 7 + kx], __ldg(&mp[HW + q]), acc);
        }
    }
    g_scale[(size_t)b * HW + hw] = 1.0f / (1.0f + __expf(-acc));
}

__device__ __forceinline__ void k3_body(const float* __restrict__ x,
                                        float* __restrict__ out, int local, int g) {
    const float4* __restrict__ xv = reinterpret_cast<const float4*>(x);
    const float4* __restrict__ sv = reinterpret_cast<const float4*>(g_scale);
    float4* __restrict__ ov = reinterpret_cast<float4*>(out);

    // plane index within whole tensor
    size_t plane = (size_t)g * N3 + local;        // 0..8191
    size_t blk   = plane << 10;                   // * 1024 float4
    int b = (int)(blk >> 18);

    float4 v[4], s[4];
    #pragma unroll
    for (int k = 0; k < 4; k++) {
        size_t i = blk + k * 256 + threadIdx.x;
        v[k] = __ldcs(&xv[i]);
        s[k] = __ldg(&sv[(size_t)b * HW4 + (i & 1023)]);
    }
    #pragma unroll
    for (int k = 0; k < 4; k++) {
        size_t i = blk + k * 256 + threadIdx.x;
        v[k].x *= s[k].x; v[k].y *= s[k].y; v[k].z *= s[k].z; v[k].w *= s[k].w;
        __stcs(&ov[i], v[k]);
    }
}

// ---------------- fat pipeline kernel ----------------
// block ranges: [0,N1) -> K1(g1), [N1,N1+N2) -> K2(g2), [N1+N2,..) -> K3(g3)
__global__ __launch_bounds__(256) void pipe_kernel(const float* __restrict__ x,
                                                   const float* __restrict__ w,
                                                   float* __restrict__ out,
                                                   int g1, int g2, int g3) {
    __shared__ float4 smax[8][32];
    __shared__ float4 ssum[8][32];

    int bid = blockIdx.x;
    if (bid < N1) {
        if (g1 >= 0 && g1 < NGROUPS)
            k1_body(x, bid, g1, smax, ssum);
    } else if (bid < N1 + N2) {
        if (g2 >= 0 && g2 < NGROUPS)
            k2_body(w, bid - N1, g2, reinterpret_cast<float*>(smax));
    } else {
        if (g3 >= 0 && g3 < NGROUPS)
            k3_body(x, out, bid - N1 - N2, g3);
    }
}

extern "C" void kernel_launch(void* const* d_in, const int* in_sizes, int n_in,
                              void* d_out, int out_size) {
    const float* x = (const float*)d_in[0];
    const float* w = (const float*)d_in[1];
    float* out = (float*)d_out;

    // Software pipeline: launch i runs K1(i), K2(i-1), K3(i-2).
    // K1's DRAM reads overlap K3's DRAM writes instead of serializing.
    for (int i = 0; i < NGROUPS + 2; i++) {
        pipe_kernel<<<N1 + N2 + N3, 256>>>(x, w, out, i, i - 1, i - 2);
    }
}